// round 8
// baseline (speedup 1.0000x reference)
#include <cuda_runtime.h>
#include <cstdint>

#define NB 64
#define TT 100
#define NN 25
#define VV 128
#define CC 128
#define EE 64
#define NG (NB*TT)
#define GPT 5                 // graphs per tile
#define MR (GPT*NN)           // 125 rows per tile
#define NTILES (NG/GPT)       // 1280
#define XSTR 132              // X/V row stride: 16B-aligned rows
#define XBUF_F (128*XSTR)     // 16896 floats per buffer
#define WS_F (VV*CC)          // 16384
#define A2D_F 1280            // 625 u64 (duplicated A2) = 1250 floats, padded
#define CNT ((float)(NB*NN*CC))

__device__ float g_A2[NN*NN];
__device__ float g_rA[NN];
__device__ float g_b1w2[CC];
__device__ float g_W12[VV*CC];
__device__ float g_stats[2*TT];

typedef unsigned long long u64;

__device__ __forceinline__ u64 pk2(float v){
    u64 r; unsigned u = __float_as_uint(v);
    asm("mov.b64 %0, {%1, %1};" : "=l"(r) : "r"(u));
    return r;
}
__device__ __forceinline__ void ffma2(u64 &d, u64 a, u64 b){
    asm("fma.rn.f32x2 %0, %1, %2, %0;" : "+l"(d) : "l"(a), "l"(b));
}
__device__ __forceinline__ void upk(u64 v, float &lo, float &hi){
    unsigned a,b; asm("mov.b64 {%0, %1}, %2;" : "=r"(a), "=r"(b) : "l"(v));
    lo = __uint_as_float(a); hi = __uint_as_float(b);
}
__device__ __forceinline__ uint32_t smem_u32(const void* p){
    uint32_t a;
    asm("{ .reg .u64 t; cvta.to.shared.u64 t, %1; cvt.u32.u64 %0, t; }" : "=r"(a) : "l"(p));
    return a;
}
__device__ __forceinline__ void cp16(uint32_t dst, const void* src){
    asm volatile("cp.async.cg.shared.global [%0], [%1], 16;" :: "r"(dst), "l"(src));
}
#define CP_COMMIT() asm volatile("cp.async.commit_group;" ::: "memory")
#define CP_WAIT0()  asm volatile("cp.async.wait_group 0;"  ::: "memory")

// ---------------------------------------------------------------------------
// Parallel prep (256 thr): every block computes one W12 row; block 0 builds
// normalized adjacency via shared atomics, A2, rowsum, b1^T W2, and zeroes
// ALL stats (replay idempotence).  Edge dtype auto-detected.
// ---------------------------------------------------------------------------
__global__ void prep_k(const int* __restrict__ ei,
                       const float* __restrict__ W1,
                       const float* __restrict__ W2,
                       const float* __restrict__ b1){
    __shared__ float A[NN*NN];
    __shared__ float row[CC];
    __shared__ float deg[NN];
    __shared__ int   es[EE], et[EE];
    __shared__ int   flag;
    const int tid = threadIdx.x;
    const int bi  = blockIdx.x;

    if (tid < CC) row[tid] = W1[bi*CC + tid];
    __syncthreads();
    if (tid < CC){
        float s = 0.0f;
        #pragma unroll 8
        for (int j = 0; j < CC; j++) s += row[j]*W2[j*CC+tid];
        g_W12[bi*CC+tid] = s;
    }

    if (bi != 0) return;

    if (tid < 2*TT) g_stats[tid] = 0.0f;
    if (tid == 0)   flag = 1;
    if (tid < NN)   deg[tid] = 1.0f;            // self-loops
    for (int i = tid; i < NN*NN; i += blockDim.x) A[i] = 0.0f;
    __syncthreads();

    if (tid < EE){  // int64 layout = [v,0] pairs in first 128 words
        int a = ei[2*tid], b = ei[2*tid+1];
        if (b != 0 || (unsigned)a >= (unsigned)NN) atomicExch(&flag, 0);
    }
    __syncthreads();
    const bool is64 = (flag != 0);
    if (tid < EE){
        es[tid] = is64 ? ei[2*tid]        : ei[tid];
        et[tid] = is64 ? ei[2*(EE+tid)]   : ei[EE+tid];
        atomicAdd(&deg[et[tid]], 1.0f);
    }
    __syncthreads();
    if (tid < EE){
        int s = es[tid], t = et[tid];
        atomicAdd(&A[t*NN+s], rsqrtf(deg[s])*rsqrtf(deg[t]));
    }
    if (tid < NN){
        float r = rsqrtf(deg[tid]);
        atomicAdd(&A[tid*NN+tid], r*r);
    }
    __syncthreads();

    for (int idx = tid; idx < NN*NN; idx += blockDim.x){
        int n = idx / NN, m = idx % NN;
        float s = 0.0f;
        #pragma unroll
        for (int j = 0; j < NN; j++) s += A[n*NN+j]*A[j*NN+m];
        g_A2[idx] = s;
    }
    if (tid < NN){
        float s = 0.0f;
        #pragma unroll
        for (int m = 0; m < NN; m++) s += A[tid*NN+m];
        g_rA[tid] = s;
    }
    if (tid < CC){
        float s = 0.0f;
        for (int k = 0; k < CC; k++) s += b1[k]*W2[k*CC+tid];
        g_b1w2[tid] = s;
    }
}

// ---------------------------------------------------------------------------
// Main persistent kernel, 512 threads (16 warps, 4/SMSP), 1 block/SM.
//   stage 1: V[125,128] = X @ W12  — per-thread 4 rows (tr+32i) x 8 cols
//            (tc*8), FFMA2; X double-buffered via cp.async.
//   stage 2: 10 warps: graph = w%5, column-half = w/5; A2 read from a
//            pre-duplicated u64 table (no per-FMA dup MOVs); 2 cols/lane.
// ---------------------------------------------------------------------------
__global__ __launch_bounds__(512, 1)
void gcn_k(const float* __restrict__ x,
           const float* __restrict__ b2g,
           float* __restrict__ out){
    extern __shared__ float sm[];
    float* ws   = sm;                 // W12 [k][c], 128x128
    float* XV0  = ws  + WS_F;         // buffer 0 (X then V), 128x132
    float* XV1  = XV0 + XBUF_F;       // buffer 1
    float* A2df = XV1 + XBUF_F;       // duplicated A2: 625 u64
    u64*   A2d  = (u64*)A2df;
    float* rAs  = A2df + A2D_F;       // 32
    float* bws  = rAs + 32;           // 128 (16B-aligned)
    float* b2s  = bws + CC;           // 128 (16B-aligned)

    const int tid  = threadIdx.x;
    const int tc   = tid & 15;
    const int tr   = tid >> 4;        // 0..31
    const int c0   = tc << 3;
    const int lane = tid & 31;
    const int wid  = tid >> 5;        // 0..15
    const uint32_t xb0 = smem_u32(XV0);
    const uint32_t xb1 = smem_u32(XV1);

    for (int i = tid; i < WS_F/4; i += 512)
        ((float4*)ws)[i] = ((const float4*)g_W12)[i];
    for (int i = tid; i < NN*NN; i += 512) A2d[i] = pk2(g_A2[i]);
    if (tid < NN) rAs[tid] = g_rA[tid];
    if (tid < CC) bws[tid] = g_b1w2[tid];
    else if (tid < 2*CC) b2s[tid-CC] = b2g[tid-CC];
    __syncthreads();

    // prologue: prefetch first tile into buffer 0
    {
        int t0 = blockIdx.x;
        if (t0 < NTILES){
            const float4* xp = (const float4*)(x + (size_t)t0*(MR*CC));
            for (int i = tid; i < (MR*CC)/4; i += 512){
                int row = i >> 5, cb = (i & 31) << 2;
                cp16(xb0 + (uint32_t)(row*XSTR + cb)*4u, xp + i);
            }
        }
        CP_COMMIT();
    }

    int it = 0;
    for (int tile = blockIdx.x; tile < NTILES; tile += gridDim.x, it++){
        const int      buf = it & 1;
        float*         Xb  = buf ? XV1 : XV0;
        const uint32_t nxb = buf ? xb0 : xb1;

        CP_WAIT0();
        __syncthreads();          // X(tile) visible; prev stage2 done

        // prefetch next tile into the other buffer
        {
            int nt = tile + gridDim.x;
            if (nt < NTILES){
                const float4* xp = (const float4*)(x + (size_t)nt*(MR*CC));
                for (int i = tid; i < (MR*CC)/4; i += 512){
                    int row = i >> 5, cb = (i & 31) << 2;
                    cp16(nxb + (uint32_t)(row*XSTR + cb)*4u, xp + i);
                }
            }
            CP_COMMIT();
        }

        // ---- stage 1: V = X @ W12 (rows tr+32i; rows 125..127 junk, never stored)
        u64 acc[4][4];
        #pragma unroll
        for (int i = 0; i < 4; i++)
            #pragma unroll
            for (int q = 0; q < 4; q++) acc[i][q] = 0ull;

        #pragma unroll 4
        for (int k = 0; k < VV; k++){
            const float* wr = ws + (k << 7) + c0;
            ulonglong2 wa = *(const ulonglong2*)wr;
            ulonglong2 wb = *(const ulonglong2*)(wr + 4);
            float af[4];
            #pragma unroll
            for (int i = 0; i < 4; i++) af[i] = Xb[(tr + 32*i)*XSTR + k];
            #pragma unroll
            for (int i = 0; i < 4; i++){
                u64 a = pk2(af[i]);
                ffma2(acc[i][0], a, wa.x);
                ffma2(acc[i][1], a, wa.y);
                ffma2(acc[i][2], a, wb.x);
                ffma2(acc[i][3], a, wb.y);
            }
        }
        __syncthreads();   // all X reads done -> reuse buffer as V

        #pragma unroll
        for (int i = 0; i < 4; i++){
            int row = tr + 32*i;
            if (i < 3 || row < MR){
                ulonglong2* vp = (ulonglong2*)(Xb + row*XSTR + c0);
                ulonglong2 t0; t0.x = acc[i][0]; t0.y = acc[i][1];
                ulonglong2 t1; t1.x = acc[i][2]; t1.y = acc[i][3];
                vp[0] = t0; vp[1] = t1;
            }
        }
        __syncthreads();

        // ---- stage 2: 10 warps; graph = wid%5, column half = wid/5 ----
        if (wid < 2*GPT){
            const int gw = wid % GPT;          // graph within tile
            const int ch = wid / GPT;          // column half
            const int g  = tile*GPT + gw;
            const int cb = ch*64 + (lane << 1); // 2 cols per lane

            u64 z[NN];
            #pragma unroll
            for (int n = 0; n < NN; n++) z[n] = 0ull;

            #pragma unroll 5
            for (int m = 0; m < NN; m++){
                u64 v = *(const u64*)(Xb + (gw*NN + m)*XSTR + cb);
                const u64* ad = A2d + m;        // A2d[n*NN+m]
                #pragma unroll
                for (int n = 0; n < NN; n++)
                    ffma2(z[n], ad[n*NN], v);
            }

            float bw0 = bws[cb], bw1 = bws[cb+1];
            float bb0 = b2s[cb], bb1 = b2s[cb+1];
            float* zp = out + (size_t)g*(NN*CC) + cb;
            float ls = 0.0f, lss = 0.0f;
            #pragma unroll
            for (int n = 0; n < NN; n++){
                float r = rAs[n];
                float o0, o1;
                upk(z[n], o0, o1);
                o0 = fmaf(r, bw0, o0) + bb0;
                o1 = fmaf(r, bw1, o1) + bb1;
                ls += o0 + o1;
                lss = fmaf(o0,o0, fmaf(o1,o1, lss));
                *(float2*)(zp + n*CC) = make_float2(o0, o1);
            }
            #pragma unroll
            for (int s = 16; s; s >>= 1){
                ls  += __shfl_xor_sync(0xffffffffu, ls,  s);
                lss += __shfl_xor_sync(0xffffffffu, lss, s);
            }
            if (lane == 0){
                int t = g % TT;
                atomicAdd(&g_stats[t],      ls);
                atomicAdd(&g_stats[TT + t], lss);
            }
        }
        __syncthreads();   // V reads done before prefetched X lands next iter
    }
}

// BN finalize (per-block redundant) + in-place BN + ReLU, 8 float4 per iter.
__global__ void bn_k(const float* __restrict__ gamma,
                     const float* __restrict__ beta,
                     float* __restrict__ out){
    __shared__ float sc[TT], sh[TT];
    for (int t = threadIdx.x; t < TT; t += blockDim.x){
        float mean = g_stats[t] / CNT;
        float var  = g_stats[TT + t] / CNT - mean*mean;
        float s    = rsqrtf(var + 1e-5f) * gamma[t];
        sc[t] = s;
        sh[t] = beta[t] - mean*s;
    }
    __syncthreads();

    const int total32 = (NB*TT*NN*CC)/32;   // 640,000 groups of 8 float4
    int stride = gridDim.x * blockDim.x;
    for (int i = blockIdx.x*blockDim.x + threadIdx.x; i < total32; i += stride){
        int t = (i / 100) % TT;             // 100 = N*C/32 groups per (b,t)
        float s = sc[t], h = sh[t];
        float4* p = (float4*)out + (size_t)i*8;
        float4 v[8];
        #pragma unroll
        for (int q = 0; q < 8; q++) v[q] = p[q];
        #pragma unroll
        for (int q = 0; q < 8; q++){
            v[q].x = fmaxf(fmaf(v[q].x, s, h), 0.0f);
            v[q].y = fmaxf(fmaf(v[q].y, s, h), 0.0f);
            v[q].z = fmaxf(fmaf(v[q].z, s, h), 0.0f);
            v[q].w = fmaxf(fmaf(v[q].w, s, h), 0.0f);
        }
        #pragma unroll
        for (int q = 0; q < 8; q++) p[q] = v[q];
    }
}

extern "C" void kernel_launch(void* const* d_in, const int* in_sizes, int n_in,
                              void* d_out, int out_size){
    const float* x  = (const float*)d_in[0];
    const int*   ei = (const int*)  d_in[1];
    const float* W1 = (const float*)d_in[2];
    const float* b1 = (const float*)d_in[3];
    const float* W2 = (const float*)d_in[4];
    const float* b2 = (const float*)d_in[5];
    const float* ga = (const float*)d_in[6];
    const float* be = (const float*)d_in[7];
    float* out = (float*)d_out;

    int nsm = 148;
    cudaDeviceGetAttribute(&nsm, cudaDevAttrMultiProcessorCount, 0);

    const int smemB = (WS_F + 2*XBUF_F + A2D_F + 32 + 2*CC) * (int)sizeof(float);
    cudaFuncSetAttribute(gcn_k, cudaFuncAttributeMaxDynamicSharedMemorySize, smemB);

    prep_k<<<CC, 256>>>(ei, W1, W2, b1);
    gcn_k<<<nsm, 512, smemB>>>(x, b2, out);
    bn_k<<<nsm*8, 256>>>(ga, be, out);
}

// round 10
// speedup vs baseline: 1.1408x; 1.1408x over previous
#include <cuda_runtime.h>
#include <cstdint>

#define NB 64
#define TT 100
#define NN 25
#define VV 128
#define CC 128
#define EE 64
#define NG (NB*TT)
#define GPT 5                 // graphs per tile
#define MR (GPT*NN)           // 125 rows per tile
#define NTILES (NG/GPT)       // 1280
#define XSTR 132              // X/V row stride: 16B-aligned rows, conflict-free broadcasts
#define XV_F (128*XSTR)       // 16896 floats
#define A2D_F 1280            // 625 u64 (duplicated A2) = 1250 floats, padded
#define CNT ((float)(NB*NN*CC))

__device__ float g_A2[NN*NN];
__device__ float g_rA[NN];
__device__ float g_b1w2[CC];
__device__ float g_W12[VV*CC];
__device__ float g_stats[2*TT];

typedef unsigned long long u64;

__device__ __forceinline__ u64 pk2(float v){
    u64 r; unsigned u = __float_as_uint(v);
    asm("mov.b64 %0, {%1, %1};" : "=l"(r) : "r"(u));
    return r;
}
__device__ __forceinline__ void ffma2(u64 &d, u64 a, u64 b){
    asm("fma.rn.f32x2 %0, %1, %2, %0;" : "+l"(d) : "l"(a), "l"(b));
}
__device__ __forceinline__ void upk(u64 v, float &lo, float &hi){
    unsigned a,b; asm("mov.b64 {%0, %1}, %2;" : "=r"(a), "=r"(b) : "l"(v));
    lo = __uint_as_float(a); hi = __uint_as_float(b);
}
__device__ __forceinline__ uint32_t smem_u32(const void* p){
    uint32_t a;
    asm("{ .reg .u64 t; cvta.to.shared.u64 t, %1; cvt.u32.u64 %0, t; }" : "=r"(a) : "l"(p));
    return a;
}
__device__ __forceinline__ void cp16(uint32_t dst, const void* src){
    asm volatile("cp.async.cg.shared.global [%0], [%1], 16;" :: "r"(dst), "l"(src));
}
#define CP_COMMIT() asm volatile("cp.async.commit_group;" ::: "memory")
#define CP_WAIT0()  asm volatile("cp.async.wait_group 0;"  ::: "memory")

// ---------------------------------------------------------------------------
// Parallel prep (256 thr): every block computes one W12 row; block 0 builds
// normalized adjacency via shared atomics, A2, rowsum, b1^T W2, and zeroes
// ALL stats (replay idempotence).  Edge dtype auto-detected.
// ---------------------------------------------------------------------------
__global__ void prep_k(const int* __restrict__ ei,
                       const float* __restrict__ W1,
                       const float* __restrict__ W2,
                       const float* __restrict__ b1){
    __shared__ float A[NN*NN];
    __shared__ float row[CC];
    __shared__ float deg[NN];
    __shared__ int   es[EE], et[EE];
    __shared__ int   flag;
    const int tid = threadIdx.x;
    const int bi  = blockIdx.x;

    if (tid < CC) row[tid] = W1[bi*CC + tid];
    __syncthreads();
    if (tid < CC){
        float s = 0.0f;
        #pragma unroll 8
        for (int j = 0; j < CC; j++) s += row[j]*W2[j*CC+tid];
        g_W12[bi*CC+tid] = s;
    }

    if (bi != 0) return;

    if (tid < 2*TT) g_stats[tid] = 0.0f;
    if (tid == 0)   flag = 1;
    if (tid < NN)   deg[tid] = 1.0f;            // self-loops
    for (int i = tid; i < NN*NN; i += blockDim.x) A[i] = 0.0f;
    __syncthreads();

    if (tid < EE){  // int64 layout = [v,0] pairs in first 128 words
        int a = ei[2*tid], b = ei[2*tid+1];
        if (b != 0 || (unsigned)a >= (unsigned)NN) atomicExch(&flag, 0);
    }
    __syncthreads();
    const bool is64 = (flag != 0);
    if (tid < EE){
        es[tid] = is64 ? ei[2*tid]        : ei[tid];
        et[tid] = is64 ? ei[2*(EE+tid)]   : ei[EE+tid];
        atomicAdd(&deg[et[tid]], 1.0f);
    }
    __syncthreads();
    if (tid < EE){
        int s = es[tid], t = et[tid];
        atomicAdd(&A[t*NN+s], rsqrtf(deg[s])*rsqrtf(deg[t]));
    }
    if (tid < NN){
        float r = rsqrtf(deg[tid]);
        atomicAdd(&A[tid*NN+tid], r*r);
    }
    __syncthreads();

    for (int idx = tid; idx < NN*NN; idx += blockDim.x){
        int n = idx / NN, m = idx % NN;
        float s = 0.0f;
        #pragma unroll
        for (int j = 0; j < NN; j++) s += A[n*NN+j]*A[j*NN+m];
        g_A2[idx] = s;
    }
    if (tid < NN){
        float s = 0.0f;
        #pragma unroll
        for (int m = 0; m < NN; m++) s += A[tid*NN+m];
        g_rA[tid] = s;
    }
    if (tid < CC){
        float s = 0.0f;
        for (int k = 0; k < CC; k++) s += b1[k]*W2[k*CC+tid];
        g_b1w2[tid] = s;
    }
}

// ---------------------------------------------------------------------------
// Main persistent kernel, 256 threads, 2 blocks/SM (smem ~71KB/block).
//   W12 is NOT in smem: read via __ldg — stays L1-resident (X staging uses
//   cp.async.cg which bypasses L1, so W12 lines are not evicted).
//   stage 1: V[125,128] = X @ W12 — 8 rows (tr+16i) x 8 cols per thread.
//   stage 2: warps 0..4, one graph each; n chunked 9/8/8 to cap registers.
// ---------------------------------------------------------------------------
__global__ __launch_bounds__(256, 2)
void gcn_k(const float* __restrict__ x,
           const float* __restrict__ b2g,
           float* __restrict__ out){
    extern __shared__ float sm[];
    float* XV   = sm;                 // X tile then V tile, 128x132
    float* A2df = XV + XV_F;          // duplicated A2: 625 u64
    u64*   A2d  = (u64*)A2df;
    float* rAs  = A2df + A2D_F;       // 32
    float* bws  = rAs + 32;           // 128
    float* b2s  = bws + CC;           // 128

    const int tid  = threadIdx.x;
    const int tc   = tid & 15;
    const int tr   = tid >> 4;        // 0..15
    const int c0   = tc << 3;
    const int lane = tid & 31;
    const int wid  = tid >> 5;        // 0..7
    const uint32_t xb = smem_u32(XV);

    for (int i = tid; i < NN*NN; i += 256) A2d[i] = pk2(g_A2[i]);
    if (tid < NN) rAs[tid] = g_rA[tid];
    if (tid < CC) bws[tid] = g_b1w2[tid];
    else if (tid < 2*CC) b2s[tid-CC] = b2g[tid-CC];
    __syncthreads();

    const ulonglong2* __restrict__ wg = (const ulonglong2*)g_W12;

    for (int tile = blockIdx.x; tile < NTILES; tile += gridDim.x){
        // ---- stage X via cp.async.cg (L1 bypass) ----
        const float4* xp = (const float4*)(x + (size_t)tile*(MR*CC));
        for (int i = tid; i < (MR*CC)/4; i += 256){
            int row = i >> 5, cb = (i & 31) << 2;
            cp16(xb + (uint32_t)(row*XSTR + cb)*4u, xp + i);
        }
        CP_COMMIT();
        CP_WAIT0();
        __syncthreads();

        // ---- stage 1: V = X @ W12 (rows tr+16i; rows 125..127 junk, never stored)
        u64 acc[8][4];
        #pragma unroll
        for (int i = 0; i < 8; i++)
            #pragma unroll
            for (int q = 0; q < 4; q++) acc[i][q] = 0ull;

        #pragma unroll 4
        for (int k = 0; k < VV; k++){
            // row k of W12 = 128 floats = 32 ulonglong2 -> k<<5 (R9 bug: was k<<4)
            const ulonglong2* wp = wg + (k << 5) + (tc << 1);
            ulonglong2 wa = __ldg(wp);
            ulonglong2 wb = __ldg(wp + 1);
            float af[8];
            #pragma unroll
            for (int i = 0; i < 8; i++) af[i] = XV[(tr + 16*i)*XSTR + k];
            #pragma unroll
            for (int i = 0; i < 8; i++){
                u64 a = pk2(af[i]);
                ffma2(acc[i][0], a, wa.x);
                ffma2(acc[i][1], a, wa.y);
                ffma2(acc[i][2], a, wb.x);
                ffma2(acc[i][3], a, wb.y);
            }
        }
        __syncthreads();   // all X reads done -> reuse buffer as V

        #pragma unroll
        for (int i = 0; i < 8; i++){
            int row = tr + 16*i;
            if (i < 7 || row < MR){
                ulonglong2* vp = (ulonglong2*)(XV + row*XSTR + c0);
                ulonglong2 t0; t0.x = acc[i][0]; t0.y = acc[i][1];
                ulonglong2 t1; t1.x = acc[i][2]; t1.y = acc[i][3];
                vp[0] = t0; vp[1] = t1;
            }
        }
        __syncthreads();

        // ---- stage 2: warps 0..4 own one graph; n chunked 9/8/8 ----
        if (wid < GPT){
            const int g  = tile*GPT + wid;
            const int cb = lane << 2;            // 4 cols per lane
            float bw0 = bws[cb],   bw1 = bws[cb+1],
                  bw2 = bws[cb+2], bw3 = bws[cb+3];
            float bb0 = b2s[cb],   bb1 = b2s[cb+1],
                  bb2 = b2s[cb+2], bb3 = b2s[cb+3];
            float* zp = out + (size_t)g*(NN*CC) + cb;
            float ls = 0.0f, lss = 0.0f;

            #pragma unroll
            for (int ch = 0; ch < 3; ch++){
                const int n0 = (ch == 0) ? 0 : 9 + (ch-1)*8;
                const int nc = (ch == 0) ? 9 : 8;
                u64 z[9][2];
                #pragma unroll
                for (int n = 0; n < 9; n++){ z[n][0] = 0ull; z[n][1] = 0ull; }

                #pragma unroll 5
                for (int m = 0; m < NN; m++){
                    ulonglong2 v = *(const ulonglong2*)(XV + (wid*NN + m)*XSTR + cb);
                    const u64* ad = A2d + (n0*NN + m);
                    #pragma unroll
                    for (int n = 0; n < 9; n++){
                        if (n < nc){
                            u64 a = ad[n*NN];
                            ffma2(z[n][0], a, v.x);
                            ffma2(z[n][1], a, v.y);
                        }
                    }
                }
                #pragma unroll
                for (int n = 0; n < 9; n++){
                    if (n < nc){
                        float r = rAs[n0 + n];
                        float o0,o1,o2,o3;
                        upk(z[n][0], o0, o1);
                        upk(z[n][1], o2, o3);
                        o0 = fmaf(r, bw0, o0) + bb0;
                        o1 = fmaf(r, bw1, o1) + bb1;
                        o2 = fmaf(r, bw2, o2) + bb2;
                        o3 = fmaf(r, bw3, o3) + bb3;
                        ls += o0 + o1 + o2 + o3;
                        lss = fmaf(o0,o0, fmaf(o1,o1, fmaf(o2,o2, fmaf(o3,o3, lss))));
                        *(float4*)(zp + (n0+n)*CC) = make_float4(o0,o1,o2,o3);
                    }
                }
            }
            #pragma unroll
            for (int s = 16; s; s >>= 1){
                ls  += __shfl_xor_sync(0xffffffffu, ls,  s);
                lss += __shfl_xor_sync(0xffffffffu, lss, s);
            }
            if (lane == 0){
                int t = g % TT;
                atomicAdd(&g_stats[t],      ls);
                atomicAdd(&g_stats[TT + t], lss);
            }
        }
        __syncthreads();   // V reads done before next tile's X staging
    }
}

// BN finalize (per-block redundant) + in-place BN + ReLU, 8 float4 per iter.
__global__ void bn_k(const float* __restrict__ gamma,
                     const float* __restrict__ beta,
                     float* __restrict__ out){
    __shared__ float sc[TT], sh[TT];
    for (int t = threadIdx.x; t < TT; t += blockDim.x){
        float mean = g_stats[t] / CNT;
        float var  = g_stats[TT + t] / CNT - mean*mean;
        float s    = rsqrtf(var + 1e-5f) * gamma[t];
        sc[t] = s;
        sh[t] = beta[t] - mean*s;
    }
    __syncthreads();

    const int total32 = (NB*TT*NN*CC)/32;   // 640,000 groups of 8 float4
    int stride = gridDim.x * blockDim.x;
    for (int i = blockIdx.x*blockDim.x + threadIdx.x; i < total32; i += stride){
        int t = (i / 100) % TT;             // 100 = N*C/32 groups per (b,t)
        float s = sc[t], h = sh[t];
        float4* p = (float4*)out + (size_t)i*8;
        float4 v[8];
        #pragma unroll
        for (int q = 0; q < 8; q++) v[q] = p[q];
        #pragma unroll
        for (int q = 0; q < 8; q++){
            v[q].x = fmaxf(fmaf(v[q].x, s, h), 0.0f);
            v[q].y = fmaxf(fmaf(v[q].y, s, h), 0.0f);
            v[q].z = fmaxf(fmaf(v[q].z, s, h), 0.0f);
            v[q].w = fmaxf(fmaf(v[q].w, s, h), 0.0f);
        }
        #pragma unroll
        for (int q = 0; q < 8; q++) p[q] = v[q];
    }
}

extern "C" void kernel_launch(void* const* d_in, const int* in_sizes, int n_in,
                              void* d_out, int out_size){
    const float* x  = (const float*)d_in[0];
    const int*   ei = (const int*)  d_in[1];
    const float* W1 = (const float*)d_in[2];
    const float* b1 = (const float*)d_in[3];
    const float* W2 = (const float*)d_in[4];
    const float* b2 = (const float*)d_in[5];
    const float* ga = (const float*)d_in[6];
    const float* be = (const float*)d_in[7];
    float* out = (float*)d_out;

    int nsm = 148;
    cudaDeviceGetAttribute(&nsm, cudaDevAttrMultiProcessorCount, 0);

    const int smemB = (XV_F + A2D_F + 32 + 2*CC) * (int)sizeof(float);
    cudaFuncSetAttribute(gcn_k, cudaFuncAttributeMaxDynamicSharedMemorySize, smemB);

    prep_k<<<CC, 256>>>(ei, W1, W2, b1);
    gcn_k<<<nsm*2, 256, smemB>>>(x, b2, out);
    bn_k<<<nsm*8, 256>>>(ga, be, out);
}